// round 15
// baseline (speedup 1.0000x reference)
#include <cuda_runtime.h>
#include <math.h>

#define NN 8192
#define DINV_C 0.011048543456039806f   /* (float)(1/sqrt(8192)) */
#define MAXD 256
#define BLKT 224        /* threads per pass block: 7 warps */
#define NW 7
#define RPB 28          /* rows per block: 7 warps x 4 */
#define GRIDP 296       /* 2 blocks/SM x 148 SMs, covers 8288 >= 8192 rows */
#define NSTAGE 4        /* cp.async ring stages per warp */

static __device__ float g_s1T[10 * NN];   // XW1 transposed [k][j], UNSCALED
static __device__ float g_U1[NN * 10];    // adj @ XW1
static __device__ float g_minrow[NN];
static __device__ float g_dinv[NN];
static __device__ int   g_defect[MAXD];
static __device__ int   g_ndef;
static __device__ int   g_done;           // pass1 finished-block counter
static __device__ float g_s2T[5 * NN];    // s2 transposed [m][j], exact
static __device__ float g_partA[64 * 5];  // sum_i dinv*s2T  (from k_h_s2)
static __device__ float g_partB[GRIDP * 5]; // sum_i dinv*U2 (from pass2 epilogue)

// ---------------------------------------------------------------------------
// packed fp32x2 FMA (FFMA2) — only reachable via PTX on sm_103a
// ---------------------------------------------------------------------------
__device__ __forceinline__ unsigned long long ffma2(unsigned long long a,
                                                    unsigned long long b,
                                                    unsigned long long c) {
    unsigned long long d;
    asm("fma.rn.f32x2 %0, %1, %2, %3;" : "=l"(d) : "l"(a), "l"(b), "l"(c));
    return d;
}
union U64F2 { unsigned long long u; float2 f; };
__device__ __forceinline__ float2 u2f(unsigned long long u) { U64F2 t; t.u = u; return t.f; }

__device__ __forceinline__ void cp_async16(unsigned dst, const float* src) {
    asm volatile("cp.async.cg.shared.global [%0], [%1], 16;" :: "r"(dst), "l"(src));
}

// ---------------------------------------------------------------------------
// K1: s1T[k][i] = (x @ W1)[i][k].  4 lanes per row.  Also resets g_done.
// ---------------------------------------------------------------------------
__global__ void __launch_bounds__(256) k_xw1(const float* __restrict__ x,
                                             const float* __restrict__ W1) {
    __shared__ float w[128 * 10];
    int tid = threadIdx.x;
    if (blockIdx.x == 0 && tid == 0) g_done = 0;    // graph-replay reset
    for (int t = tid; t < 128 * 10; t += 256) w[t] = W1[t];
    __syncthreads();
    int g = blockIdx.x * 256 + tid;          // 0..32767
    int i = g >> 2, q = g & 3;               // row, quarter
    float acc[10];
#pragma unroll
    for (int k = 0; k < 10; k++) acc[k] = 0.f;
    const float4* xr = (const float4*)(x + (size_t)i * 128 + q * 32);
#pragma unroll
    for (int c4 = 0; c4 < 8; c4++) {
        float4 xv = xr[c4];
        int cb = (q * 32 + c4 * 4) * 10;
#pragma unroll
        for (int k = 0; k < 10; k++) {
            acc[k] += xv.x * w[cb + k];
            acc[k] += xv.y * w[cb + 10 + k];
            acc[k] += xv.z * w[cb + 20 + k];
            acc[k] += xv.w * w[cb + 30 + k];
        }
    }
#pragma unroll
    for (int k = 0; k < 10; k++) {
        acc[k] += __shfl_xor_sync(0xffffffffu, acc[k], 1);
        acc[k] += __shfl_xor_sync(0xffffffffu, acc[k], 2);
    }
    if (q == 0)
#pragma unroll
        for (int k = 0; k < 10; k++) g_s1T[k * NN + i] = acc[k];
}

// ---------------------------------------------------------------------------
// Main pass: U[i][k] = sum_j adj[i][j] * sT[k][j]
// 224 thr (7 warps x 4 rows = 28 rows), grid 296 = TWO CTAs/SM, one wave.
// 4-stage cp.async ring (3-segment lookahead, ~84KB/SM in flight) + cross-
// block overlap hides DRAM latency through barriers and waits.
// PASS1 (TRACK): per-row min; LAST finishing block runs scan+recount inline.
// PASS2: skips U global writes; per-block partB = sum dinv*U2 instead.
// ---------------------------------------------------------------------------
template <int KT, int JTILE, bool TRACK, int PASS>
__global__ void __launch_bounds__(BLKT, 2) k_pass(const float* __restrict__ adj) {
    const float* __restrict__ sT = (PASS == 1) ? g_s1T : g_s2T;
    extern __shared__ __align__(16) float smem[];
    float* tile = smem;                                   // KT*JTILE floats
    const int tid  = threadIdx.x;
    const int warp = tid >> 5, lane = tid & 31;
    float* abuf = smem + KT * JTILE + warp * (NSTAGE * 512);
    const unsigned abase = (unsigned)__cvta_generic_to_shared(abuf);

    const int row0 = blockIdx.x * RPB + warp * 4;
    const int row0c = (row0 > NN - 4) ? (NN - 4) : row0;   // clamp: dup reads
    const bool ok = (row0 < NN);
    const float* __restrict__ rp = adj + (size_t)row0c * NN;

    unsigned long long acc[4][KT];
#pragma unroll
    for (int r = 0; r < 4; r++)
#pragma unroll
        for (int k = 0; k < KT; k++) acc[r][k] = 0ull;

    float rmin[4];
#pragma unroll
    for (int r = 0; r < 4; r++) rmin[r] = 3.4e38f;

    constexpr int NSEG = NN / 128;
    constexpr int IPT  = JTILE / 128;
    constexpr int NT   = NN / JTILE;

    // load tile 0 (L2-resident sT)
    for (int idx = tid; idx < KT * (JTILE / 4); idx += BLKT) {
        int k = idx / (JTILE / 4), q = idx % (JTILE / 4);
        ((float4*)tile)[idx] = ((const float4*)(sT + (size_t)k * NN))[q];
    }

    // cp.async prologue: segments 0..NSTAGE-1
#pragma unroll
    for (int s = 0; s < NSTAGE; s++) {
#pragma unroll
        for (int r = 0; r < 4; r++)
            cp_async16(abase + (unsigned)((s * 512 + r * 128 + lane * 4) * 4),
                       rp + (size_t)r * NN + s * 128 + lane * 4);
        asm volatile("cp.async.commit_group;");
    }
    __syncthreads();

    for (int tI = 0; tI < NT; tI++) {
        if (tI > 0) {
            __syncthreads();
            for (int idx = tid; idx < KT * (JTILE / 4); idx += BLKT) {
                int k = idx / (JTILE / 4), q = idx % (JTILE / 4);
                ((float4*)tile)[idx] =
                    ((const float4*)(sT + (size_t)k * NN + (size_t)tI * JTILE))[q];
            }
            __syncthreads();
        }
#pragma unroll 2
        for (int it = 0; it < IPT; it++) {
            const int seg = tI * IPT + it;
            asm volatile("cp.async.wait_group %0;" :: "n"(NSTAGE - 1));
            longlong2 a[4];
#pragma unroll
            for (int r = 0; r < 4; r++)
                a[r] = *(const longlong2*)(abuf + (seg & (NSTAGE - 1)) * 512 + r * 128 + lane * 4);
            {
                const int sn = seg + NSTAGE;
                const int goff = (sn < NSEG) ? sn * 128 : 0;
#pragma unroll
                for (int r = 0; r < 4; r++)
                    cp_async16(abase + (unsigned)(((sn & (NSTAGE - 1)) * 512 + r * 128 + lane * 4) * 4),
                               rp + (size_t)r * NN + goff + lane * 4);
                asm volatile("cp.async.commit_group;");
            }
            if (TRACK) {
#pragma unroll
                for (int r = 0; r < 4; r++) {
                    float2 lo = u2f((unsigned long long)a[r].x);
                    float2 hi = u2f((unsigned long long)a[r].y);
                    rmin[r] = fminf(rmin[r], fminf(fminf(lo.x, lo.y), fminf(hi.x, hi.y)));
                }
            }
            const int js = it * 128 + lane * 4;
#pragma unroll
            for (int k = 0; k < KT; k++) {
                longlong2 sv = *(const longlong2*)&tile[k * JTILE + js];
#pragma unroll
                for (int r = 0; r < 4; r++) {
                    acc[r][k] = ffma2((unsigned long long)a[r].x, (unsigned long long)sv.x, acc[r][k]);
                    acc[r][k] = ffma2((unsigned long long)a[r].y, (unsigned long long)sv.y, acc[r][k]);
                }
            }
        }
    }
    asm volatile("cp.async.wait_group 0;");

    // ----- epilogue -----
    __shared__ float pbs[NW][5];
    float pb[5];
    if (PASS == 2) {
#pragma unroll
        for (int k = 0; k < 5; k++) pb[k] = 0.f;
    }
#pragma unroll
    for (int r = 0; r < 4; r++) {
        float drow = 0.f;
        if (PASS == 2 && lane == 0 && ok) drow = g_dinv[row0c + r];
#pragma unroll
        for (int k = 0; k < KT; k++) {
            float2 v = u2f(acc[r][k]);
            float s = v.x + v.y;
#pragma unroll
            for (int o = 16; o > 0; o >>= 1) s += __shfl_xor_sync(0xffffffffu, s, o);
            if (PASS == 1) {
                if (lane == 0 && ok) g_U1[(size_t)(row0c + r) * KT + k] = s;
            } else {
                if (lane == 0) pb[k] += drow * s;   // drow==0 when !ok
            }
        }
        if (TRACK) {
            float m = rmin[r];
#pragma unroll
            for (int o = 16; o > 0; o >>= 1) m = fminf(m, __shfl_xor_sync(0xffffffffu, m, o));
            if (lane == 0 && ok) g_minrow[row0c + r] = m;
        }
    }
    if (PASS == 2) {
        if (lane == 0)
#pragma unroll
            for (int k = 0; k < 5; k++) pbs[warp][k] = pb[k];
        __syncthreads();
        if (tid < 5) {
            float t = 0.f;
            for (int w = 0; w < NW; w++) t += pbs[w][tid];
            g_partB[blockIdx.x * 5 + tid] = t;
        }
    }

    // ----- fused scan: last finishing pass1 block does dinv + defects -----
    if (TRACK) {
        __threadfence();
        __syncthreads();
        __shared__ int s_go;
        if (tid == 0) s_go = (atomicAdd(&g_done, 1) == GRIDP - 1) ? 1 : 0;
        __syncthreads();
        if (s_go) {
            __shared__ int wcnt[NW], woff[NW], sbase;
            if (tid == 0) sbase = 0;
            __syncthreads();
            for (int chunk = 0; chunk < NN; chunk += BLKT) {
                int i = chunk + tid;
                bool valid = (i < NN);
                bool f = valid && (g_minrow[i] <= 0.0f);
                if (valid) g_dinv[i] = DINV_C;
                unsigned m = __ballot_sync(0xffffffffu, f);
                if (lane == 0) wcnt[warp] = __popc(m);
                __syncthreads();
                if (tid == 0) {
                    int o = sbase;
                    for (int q = 0; q < NW; q++) { woff[q] = o; o += wcnt[q]; }
                    sbase = o;
                }
                __syncthreads();
                if (f) {
                    int pos = woff[warp] + __popc(m & ((1u << lane) - 1u));
                    if (pos < MAXD) g_defect[pos] = i;
                }
                __syncthreads();
            }
            int nd = (sbase > MAXD) ? MAXD : sbase;
            if (tid == 0) g_ndef = nd;
            // exact recount: one warp per defect row (coalesced reads)
            for (int d = warp; d < nd; d += NW) {
                int j = g_defect[d];
                const float4* row = (const float4*)(adj + (size_t)j * NN);
                int cnt = 0;
                for (int t = lane; t < NN / 4; t += 32) {
                    float4 v = row[t];
                    cnt += (v.x > 0.f) + (v.y > 0.f) + (v.z > 0.f) + (v.w > 0.f);
                }
#pragma unroll
                for (int o = 16; o > 0; o >>= 1) cnt += __shfl_xor_sync(0xffffffffu, cnt, o);
                if (lane == 0)
                    g_dinv[j] = (cnt > 0) ? (1.0f / sqrtf((float)cnt))
                                          : __int_as_float(0x7f800000);
            }
        }
    }
}

// ---------------------------------------------------------------------------
// K5: defect correction + h = relu(gcn1) + s2T = (h@W2)*dinv (transposed)
// Also emits per-block partA[m] = sum_i dinv_i * s2T[m][i].
// ---------------------------------------------------------------------------
__global__ void __launch_bounds__(128) k_h_s2(const float* __restrict__ adj,
                                              const float* __restrict__ b1,
                                              const float* __restrict__ W2) {
    __shared__ float sb1[10], sW2[50];
    __shared__ int   sjd[MAXD];
    __shared__ float sdv[MAXD];
    __shared__ float sxw[MAXD * 10];
    __shared__ int   snd;
    __shared__ float wsA[4][5];
    int tid = threadIdx.x, lane = tid & 31, w = tid >> 5;
    if (tid < 10) sb1[tid] = b1[tid];
    if (tid < 50) sW2[tid] = W2[tid];
    if (tid == 0) { int n = g_ndef; snd = (n > MAXD) ? MAXD : n; }
    __syncthreads();
    int nd = snd;
    for (int d = tid; d < nd; d += blockDim.x) {
        int j = g_defect[d];
        sjd[d] = j;
        sdv[d] = g_dinv[j] - DINV_C;
        for (int k = 0; k < 10; k++) sxw[d * 10 + k] = g_s1T[k * NN + j];
    }
    __syncthreads();

    int i = blockIdx.x * blockDim.x + tid;
    float di = g_dinv[i];
    float u[10];
#pragma unroll
    for (int k = 0; k < 10; k++) u[k] = DINV_C * g_U1[(size_t)i * 10 + k];
    int d = 0;
    for (; d + 3 < nd; d += 4) {
        float a0 = adj[(size_t)i * NN + sjd[d]]     * sdv[d];
        float a1 = adj[(size_t)i * NN + sjd[d + 1]] * sdv[d + 1];
        float a2 = adj[(size_t)i * NN + sjd[d + 2]] * sdv[d + 2];
        float a3 = adj[(size_t)i * NN + sjd[d + 3]] * sdv[d + 3];
#pragma unroll
        for (int k = 0; k < 10; k++)
            u[k] += a0 * sxw[d * 10 + k] + a1 * sxw[(d + 1) * 10 + k]
                  + a2 * sxw[(d + 2) * 10 + k] + a3 * sxw[(d + 3) * 10 + k];
    }
    for (; d < nd; d++) {
        float a = adj[(size_t)i * NN + sjd[d]] * sdv[d];
#pragma unroll
        for (int k = 0; k < 10; k++) u[k] += a * sxw[d * 10 + k];
    }
    float h[10];
#pragma unroll
    for (int k = 0; k < 10; k++) {
        float self = g_s1T[k * NN + i] * di;
        float v = di * (u[k] + self) + sb1[k];
        h[k] = v > 0.f ? v : 0.f;
    }
    float pa[5];
#pragma unroll
    for (int m = 0; m < 5; m++) {
        float s = 0.f;
#pragma unroll
        for (int k = 0; k < 10; k++) s += h[k] * sW2[k * 5 + m];
        float val = s * di;
        g_s2T[m * NN + i] = val;
        pa[m] = di * val;           // dinv_i * s2T[m][i]
    }
    // block-reduce partA
#pragma unroll
    for (int m = 0; m < 5; m++) {
        float v = pa[m];
#pragma unroll
        for (int o = 16; o > 0; o >>= 1) v += __shfl_xor_sync(0xffffffffu, v, o);
        if (lane == 0) wsA[w][m] = v;
    }
    __syncthreads();
    if (tid < 5)
        g_partA[blockIdx.x * 5 + tid] = wsA[0][tid] + wsA[1][tid] + wsA[2][tid] + wsA[3][tid];
}

// ---------------------------------------------------------------------------
// K6: finish mean + tiny MLP head, writes 7 outputs
// ---------------------------------------------------------------------------
__global__ void __launch_bounds__(32) k_final_b(const float* __restrict__ b2,
                                                const float* __restrict__ fc1W,
                                                const float* __restrict__ fc1b,
                                                const float* __restrict__ fcW,
                                                const float* __restrict__ fcb,
                                                float* __restrict__ out, int out_size) {
    if (threadIdx.x == 0) {
        float z[5], z2[5];
        for (int m = 0; m < 5; m++) {
            float t = 0.f;
            for (int q = 0; q < 64; q++)    t += g_partA[q * 5 + m];
            for (int q = 0; q < GRIDP; q++) t += g_partB[q * 5 + m];
            t = t * (1.0f / (float)NN) + b2[m];
            z[m] = t > 0.f ? t : 0.f;
        }
        for (int j = 0; j < 5; j++) {
            float a = fc1b[j];
            for (int m = 0; m < 5; m++) a += z[m] * fc1W[m * 5 + j];
            z2[j] = a > 0.f ? a : 0.f;
        }
        float y[2];
        for (int t2 = 0; t2 < 2; t2++) {
            float a = fcb[t2];
            for (int j = 0; j < 5; j++) a += z2[j] * fcW[j * 2 + t2];
            y[t2] = 1.0f / (1.0f + expf(-a));
        }
        for (int m = 0; m < 5; m++) if (m < out_size) out[m] = z[m];
        if (out_size > 5) out[5] = y[0];
        if (out_size > 6) out[6] = y[1];
    }
}

// ---------------------------------------------------------------------------
extern "C" void kernel_launch(void* const* d_in, const int* in_sizes, int n_in,
                              void* d_out, int out_size) {
    const float* x    = (const float*)d_in[0];
    const float* adj  = (const float*)d_in[1];
    const float* W1   = (const float*)d_in[2];
    const float* b1   = (const float*)d_in[3];
    const float* W2   = (const float*)d_in[4];
    const float* b2   = (const float*)d_in[5];
    const float* fc1W = (const float*)d_in[6];
    const float* fc1b = (const float*)d_in[7];
    const float* fcW  = (const float*)d_in[8];
    const float* fcb  = (const float*)d_in[9];
    float* out = (float*)d_out;

    // per-block: ring = 7 warps * 4 stages * 512 f * 4B = 56KB
    // pass1: KT=10, JTILE=1024 -> 40KB tile + 56KB = 96KB  (2 blocks/SM = 192KB)
    // pass2: KT=5,  JTILE=2048 -> 40KB tile + 56KB = 96KB
    const int ring = NW * NSTAGE * 512 * 4;
    const int smem1 = 10 * 1024 * 4 + ring;
    const int smem2 = 5 * 2048 * 4 + ring;
    cudaFuncSetAttribute(k_pass<10, 1024, true, 1>,
                         cudaFuncAttributeMaxDynamicSharedMemorySize, smem1);
    cudaFuncSetAttribute(k_pass<5, 2048, false, 2>,
                         cudaFuncAttributeMaxDynamicSharedMemorySize, smem2);

    k_xw1<<<128, 256>>>(x, W1);                      // also resets g_done
    k_pass<10, 1024, true, 1><<<GRIDP, BLKT, smem1>>>(adj);   // + fused scan
    k_h_s2<<<64, 128>>>(adj, b1, W2);                // + partA
    k_pass<5, 2048, false, 2><<<GRIDP, BLKT, smem2>>>(adj);   // + partB, no U2
    k_final_b<<<1, 32>>>(b2, fc1W, fc1b, fcW, fcb, out, out_size);
}

// round 16
// speedup vs baseline: 1.3522x; 1.3522x over previous
#include <cuda_runtime.h>
#include <math.h>

#define NN 8192
#define DINV_C 0.011048543456039806f   /* (float)(1/sqrt(8192)) */
#define MAXD 256
#define BLKT 448        /* 14 warps */
#define NW 14
#define RPB 56          /* 14 warps x 4 rows */
#define GRIDP 147       /* ceil(8192/56) <= 148 SMs -> single wave */
#define NSTAGE 2        /* cp.async ring stages per warp */
#define KT 10
#define JTILE 1024
#define IPT (JTILE / 128)
#define NT  (NN / JTILE)

static __device__ float g_s1T[10 * NN];   // XW1 transposed [k][j], UNSCALED
static __device__ float g_U1[NN * 10];    // adj @ XW1
static __device__ float g_minrow[NN];
static __device__ float g_dinv[NN];
static __device__ int   g_defect[MAXD];
static __device__ int   g_ndef;
static __device__ int   g_done;           // pass1 finished-block counter
static __device__ float g_colpart[(size_t)GRIDP * NN];  // per-block colsum partials
static __device__ float g_partA[64 * 5];  // sum_i dinv_i * s2[i,m]
static __device__ float g_partC[64 * 5];  // sum_j c_j   * s2[j,m]

// ---------------------------------------------------------------------------
// packed fp32x2 ops — only reachable via PTX on sm_103a
// ---------------------------------------------------------------------------
__device__ __forceinline__ unsigned long long ffma2(unsigned long long a,
                                                    unsigned long long b,
                                                    unsigned long long c) {
    unsigned long long d;
    asm("fma.rn.f32x2 %0, %1, %2, %3;" : "=l"(d) : "l"(a), "l"(b), "l"(c));
    return d;
}
__device__ __forceinline__ unsigned long long fadd2(unsigned long long a,
                                                    unsigned long long b) {
    unsigned long long d;
    asm("add.rn.f32x2 %0, %1, %2;" : "=l"(d) : "l"(a), "l"(b));
    return d;
}
union U64F2 { unsigned long long u; float2 f; };
__device__ __forceinline__ float2 u2f(unsigned long long u) { U64F2 t; t.u = u; return t.f; }

__device__ __forceinline__ void cp_async16(unsigned dst, const float* src) {
    asm volatile("cp.async.cg.shared.global [%0], [%1], 16;" :: "r"(dst), "l"(src));
}

// ---------------------------------------------------------------------------
// K1: s1T[k][i] = (x @ W1)[i][k].  4 lanes per row.  Also resets g_done.
// ---------------------------------------------------------------------------
__global__ void __launch_bounds__(256) k_xw1(const float* __restrict__ x,
                                             const float* __restrict__ W1) {
    __shared__ float w[128 * 10];
    int tid = threadIdx.x;
    if (blockIdx.x == 0 && tid == 0) g_done = 0;    // graph-replay reset
    for (int t = tid; t < 128 * 10; t += 256) w[t] = W1[t];
    __syncthreads();
    int g = blockIdx.x * 256 + tid;          // 0..32767
    int i = g >> 2, q = g & 3;               // row, quarter
    float acc[10];
#pragma unroll
    for (int k = 0; k < 10; k++) acc[k] = 0.f;
    const float4* xr = (const float4*)(x + (size_t)i * 128 + q * 32);
#pragma unroll
    for (int c4 = 0; c4 < 8; c4++) {
        float4 xv = xr[c4];
        int cb = (q * 32 + c4 * 4) * 10;
#pragma unroll
        for (int k = 0; k < 10; k++) {
            acc[k] += xv.x * w[cb + k];
            acc[k] += xv.y * w[cb + 10 + k];
            acc[k] += xv.z * w[cb + 20 + k];
            acc[k] += xv.w * w[cb + 30 + k];
        }
    }
#pragma unroll
    for (int k = 0; k < 10; k++) {
        acc[k] += __shfl_xor_sync(0xffffffffu, acc[k], 1);
        acc[k] += __shfl_xor_sync(0xffffffffu, acc[k], 2);
    }
    if (q == 0)
#pragma unroll
        for (int k = 0; k < 10; k++) g_s1T[k * NN + i] = acc[k];
}

// ---------------------------------------------------------------------------
// THE single adj pass: U1[i][k] = sum_j adj[i][j]*s1T[k][j], per-row min,
// AND per-block column sums (adj read once, total 256MB DRAM).
// 448 thr x 4 rows = 56 rows/block, grid 147 -> one wave. cp.async 2-stage
// ring. Column sums: per-warp private smem strips (f32x2 RMW, no atomics),
// reduced at tile boundaries into g_colpart[block][j] (deterministic).
// LAST finishing block runs dinv scan + defect recount inline.
// ---------------------------------------------------------------------------
__global__ void __launch_bounds__(BLKT, 1) k_pass1(const float* __restrict__ adj) {
    extern __shared__ __align__(16) float smem[];
    float* tile   = smem;                               // KT*JTILE
    float* ring   = smem + KT * JTILE;                  // NW*NSTAGE*512
    float* strips = ring + NW * NSTAGE * 512;           // NW*JTILE
    const int tid  = threadIdx.x;
    const int warp = tid >> 5, lane = tid & 31;
    float* abuf = ring + warp * (NSTAGE * 512);
    float* mystrip = strips + warp * JTILE;
    const unsigned abase = (unsigned)__cvta_generic_to_shared(abuf);

    const int row0 = blockIdx.x * RPB + warp * 4;
    const int row0c = (row0 > NN - 4) ? (NN - 4) : row0;   // clamp: dup reads
    const bool ok = (row0 < NN);
    const float* __restrict__ rp = adj + (size_t)row0c * NN;

    unsigned long long acc[4][KT];
#pragma unroll
    for (int r = 0; r < 4; r++)
#pragma unroll
        for (int k = 0; k < KT; k++) acc[r][k] = 0ull;

    float rmin[4];
#pragma unroll
    for (int r = 0; r < 4; r++) rmin[r] = 3.4e38f;

    const int NSEG = NN / 128;

    // zero strips + load tile 0
    for (int idx = tid; idx < NW * JTILE / 4; idx += BLKT)
        ((float4*)strips)[idx] = make_float4(0.f, 0.f, 0.f, 0.f);
    for (int idx = tid; idx < KT * (JTILE / 4); idx += BLKT) {
        int k = idx / (JTILE / 4), q = idx % (JTILE / 4);
        ((float4*)tile)[idx] = ((const float4*)(g_s1T + (size_t)k * NN))[q];
    }

    // cp.async prologue
#pragma unroll
    for (int s = 0; s < NSTAGE; s++) {
#pragma unroll
        for (int r = 0; r < 4; r++)
            cp_async16(abase + (unsigned)((s * 512 + r * 128 + lane * 4) * 4),
                       rp + (size_t)r * NN + s * 128 + lane * 4);
        asm volatile("cp.async.commit_group;");
    }
    __syncthreads();

    for (int tI = 0; tI < NT; tI++) {
        if (tI > 0) {
            __syncthreads();
            for (int idx = tid; idx < KT * (JTILE / 4); idx += BLKT) {
                int k = idx / (JTILE / 4), q = idx % (JTILE / 4);
                ((float4*)tile)[idx] =
                    ((const float4*)(g_s1T + (size_t)k * NN + (size_t)tI * JTILE))[q];
            }
            __syncthreads();
        }
#pragma unroll 2
        for (int it = 0; it < IPT; it++) {
            const int seg = tI * IPT + it;
            const int js = it * 128 + lane * 4;
            asm volatile("cp.async.wait_group %0;" :: "n"(NSTAGE - 1));
            longlong2 a[4];
#pragma unroll
            for (int r = 0; r < 4; r++)
                a[r] = *(const longlong2*)(abuf + (seg & (NSTAGE - 1)) * 512 + r * 128 + lane * 4);
            {
                const int sn = seg + NSTAGE;
                const int goff = (sn < NSEG) ? sn * 128 : 0;
#pragma unroll
                for (int r = 0; r < 4; r++)
                    cp_async16(abase + (unsigned)(((sn & (NSTAGE - 1)) * 512 + r * 128 + lane * 4) * 4),
                               rp + (size_t)r * NN + goff + lane * 4);
                asm volatile("cp.async.commit_group;");
            }
            // per-row min tracking
#pragma unroll
            for (int r = 0; r < 4; r++) {
                float2 lo = u2f((unsigned long long)a[r].x);
                float2 hi = u2f((unsigned long long)a[r].y);
                rmin[r] = fminf(rmin[r], fminf(fminf(lo.x, lo.y), fminf(hi.x, hi.y)));
            }
            // column-sum strip accumulate (4-row packed sum, private strip)
            if (ok) {
                unsigned long long s0 = fadd2(
                    fadd2((unsigned long long)a[0].x, (unsigned long long)a[1].x),
                    fadd2((unsigned long long)a[2].x, (unsigned long long)a[3].x));
                unsigned long long s1 = fadd2(
                    fadd2((unsigned long long)a[0].y, (unsigned long long)a[1].y),
                    fadd2((unsigned long long)a[2].y, (unsigned long long)a[3].y));
                longlong2* sp = (longlong2*)&mystrip[js];
                longlong2 old = *sp;
                old.x = (long long)fadd2((unsigned long long)old.x, s0);
                old.y = (long long)fadd2((unsigned long long)old.y, s1);
                *sp = old;
            }
#pragma unroll
            for (int k = 0; k < KT; k++) {
                longlong2 sv = *(const longlong2*)&tile[k * JTILE + js];
#pragma unroll
                for (int r = 0; r < 4; r++) {
                    acc[r][k] = ffma2((unsigned long long)a[r].x, (unsigned long long)sv.x, acc[r][k]);
                    acc[r][k] = ffma2((unsigned long long)a[r].y, (unsigned long long)sv.y, acc[r][k]);
                }
            }
        }
        // tile end: reduce 14 strips -> per-block colsum partial, zero strips
        __syncthreads();
        {
            const size_t gbase = (size_t)blockIdx.x * NN + (size_t)tI * JTILE;
            for (int idx = tid; idx < JTILE; idx += BLKT) {
                float s = 0.f;
#pragma unroll
                for (int w = 0; w < NW; w++) {
                    s += strips[w * JTILE + idx];
                    strips[w * JTILE + idx] = 0.f;
                }
                g_colpart[gbase + idx] = s;
            }
        }
    }
    asm volatile("cp.async.wait_group 0;");   // drain dummies

    // epilogue: U1 + minrow
#pragma unroll
    for (int r = 0; r < 4; r++) {
#pragma unroll
        for (int k = 0; k < KT; k++) {
            float2 v = u2f(acc[r][k]);
            float s = v.x + v.y;
#pragma unroll
            for (int o = 16; o > 0; o >>= 1) s += __shfl_xor_sync(0xffffffffu, s, o);
            if (lane == 0 && ok) g_U1[(size_t)(row0c + r) * KT + k] = s;
        }
        float m = rmin[r];
#pragma unroll
        for (int o = 16; o > 0; o >>= 1) m = fminf(m, __shfl_xor_sync(0xffffffffu, m, o));
        if (lane == 0 && ok) g_minrow[row0c + r] = m;
    }

    // fused scan: last finishing block does dinv + defects + recount
    __threadfence();
    __syncthreads();
    __shared__ int s_go;
    if (tid == 0) s_go = (atomicAdd(&g_done, 1) == GRIDP - 1) ? 1 : 0;
    __syncthreads();
    if (s_go) {
        __shared__ int wcnt[NW], woff[NW], sbase;
        if (tid == 0) sbase = 0;
        __syncthreads();
        for (int chunk = 0; chunk < NN; chunk += BLKT) {
            int i = chunk + tid;
            bool valid = (i < NN);
            bool f = valid && (g_minrow[i] <= 0.0f);
            if (valid) g_dinv[i] = DINV_C;
            unsigned m = __ballot_sync(0xffffffffu, f);
            if (lane == 0) wcnt[warp] = __popc(m);
            __syncthreads();
            if (tid == 0) {
                int o = sbase;
                for (int q = 0; q < NW; q++) { woff[q] = o; o += wcnt[q]; }
                sbase = o;
            }
            __syncthreads();
            if (f) {
                int pos = woff[warp] + __popc(m & ((1u << lane) - 1u));
                if (pos < MAXD) g_defect[pos] = i;
            }
            __syncthreads();
        }
        int nd = (sbase > MAXD) ? MAXD : sbase;
        if (tid == 0) g_ndef = nd;
        // exact recount: one warp per defect row (coalesced reads)
        for (int d = warp; d < nd; d += NW) {
            int j = g_defect[d];
            const float4* row = (const float4*)(adj + (size_t)j * NN);
            int cnt = 0;
            for (int t = lane; t < NN / 4; t += 32) {
                float4 v = row[t];
                cnt += (v.x > 0.f) + (v.y > 0.f) + (v.z > 0.f) + (v.w > 0.f);
            }
#pragma unroll
            for (int o = 16; o > 0; o >>= 1) cnt += __shfl_xor_sync(0xffffffffu, cnt, o);
            if (lane == 0)
                g_dinv[j] = (cnt > 0) ? (1.0f / sqrtf((float)cnt))
                                      : __int_as_float(0x7f800000);
        }
    }
}

// ---------------------------------------------------------------------------
// K5: c[j] = DINV_C*colsum[j] + sum_d (dinv_d-DINV_C)*adj[j_d][j];
//     defect correction + h = relu(gcn1) + s2 value; emits
//     partA[m] = sum_i dinv_i*s2[i,m]  and  partC[m] = sum_j c_j*s2[j,m].
// ---------------------------------------------------------------------------
__global__ void __launch_bounds__(128) k_h_s2(const float* __restrict__ adj,
                                              const float* __restrict__ b1,
                                              const float* __restrict__ W2) {
    __shared__ float sb1[10], sW2[50];
    __shared__ int   sjd[MAXD];
    __shared__ float sdv[MAXD];
    __shared__ float sxw[MAXD * 10];
    __shared__ int   snd;
    __shared__ float wsA[4][5], wsC[4][5];
    int tid = threadIdx.x, lane = tid & 31, w = tid >> 5;
    if (tid < 10) sb1[tid] = b1[tid];
    if (tid < 50) sW2[tid] = W2[tid];
    if (tid == 0) { int n = g_ndef; snd = (n > MAXD) ? MAXD : n; }
    __syncthreads();
    int nd = snd;
    for (int d = tid; d < nd; d += blockDim.x) {
        int j = g_defect[d];
        sjd[d] = j;
        sdv[d] = g_dinv[j] - DINV_C;
        for (int k = 0; k < 10; k++) sxw[d * 10 + k] = g_s1T[k * NN + j];
    }
    __syncthreads();

    int i = blockIdx.x * blockDim.x + tid;
    float di = g_dinv[i];

    // c[i]: reduce the 147 per-block colsum partials (fixed order) + defect rows
    float cs = 0.f;
#pragma unroll 7
    for (int b = 0; b < GRIDP; b++) cs += g_colpart[(size_t)b * NN + i];
    float ci = DINV_C * cs;
    for (int d = 0; d < nd; d++)
        ci += sdv[d] * adj[(size_t)sjd[d] * NN + i];   // coalesced row reads

    // gcn1 defect correction (column gathers) + h
    float u[10];
#pragma unroll
    for (int k = 0; k < 10; k++) u[k] = DINV_C * g_U1[(size_t)i * 10 + k];
    int d = 0;
    for (; d + 3 < nd; d += 4) {
        float a0 = adj[(size_t)i * NN + sjd[d]]     * sdv[d];
        float a1 = adj[(size_t)i * NN + sjd[d + 1]] * sdv[d + 1];
        float a2 = adj[(size_t)i * NN + sjd[d + 2]] * sdv[d + 2];
        float a3 = adj[(size_t)i * NN + sjd[d + 3]] * sdv[d + 3];
#pragma unroll
        for (int k = 0; k < 10; k++)
            u[k] += a0 * sxw[d * 10 + k] + a1 * sxw[(d + 1) * 10 + k]
                  + a2 * sxw[(d + 2) * 10 + k] + a3 * sxw[(d + 3) * 10 + k];
    }
    for (; d < nd; d++) {
        float a = adj[(size_t)i * NN + sjd[d]] * sdv[d];
#pragma unroll
        for (int k = 0; k < 10; k++) u[k] += a * sxw[d * 10 + k];
    }
    float h[10];
#pragma unroll
    for (int k = 0; k < 10; k++) {
        float self = g_s1T[k * NN + i] * di;
        float v = di * (u[k] + self) + sb1[k];
        h[k] = v > 0.f ? v : 0.f;
    }
    float pa[5], pc[5];
#pragma unroll
    for (int m = 0; m < 5; m++) {
        float s = 0.f;
#pragma unroll
        for (int k = 0; k < 10; k++) s += h[k] * sW2[k * 5 + m];
        float val = s * di;        // s2[i][m]
        pa[m] = di * val;
        pc[m] = ci * val;
    }
#pragma unroll
    for (int m = 0; m < 5; m++) {
        float va = pa[m], vc = pc[m];
#pragma unroll
        for (int o = 16; o > 0; o >>= 1) {
            va += __shfl_xor_sync(0xffffffffu, va, o);
            vc += __shfl_xor_sync(0xffffffffu, vc, o);
        }
        if (lane == 0) { wsA[w][m] = va; wsC[w][m] = vc; }
    }
    __syncthreads();
    if (tid < 5) {
        g_partA[blockIdx.x * 5 + tid] = wsA[0][tid] + wsA[1][tid] + wsA[2][tid] + wsA[3][tid];
        g_partC[blockIdx.x * 5 + tid] = wsC[0][tid] + wsC[1][tid] + wsC[2][tid] + wsC[3][tid];
    }
}

// ---------------------------------------------------------------------------
// K6: finish mean + tiny MLP head, writes 7 outputs
// ---------------------------------------------------------------------------
__global__ void __launch_bounds__(32) k_final_b(const float* __restrict__ b2,
                                                const float* __restrict__ fc1W,
                                                const float* __restrict__ fc1b,
                                                const float* __restrict__ fcW,
                                                const float* __restrict__ fcb,
                                                float* __restrict__ out, int out_size) {
    if (threadIdx.x == 0) {
        float z[5], z2[5];
        for (int m = 0; m < 5; m++) {
            float t = 0.f;
            for (int q = 0; q < 64; q++) t += g_partA[q * 5 + m] + g_partC[q * 5 + m];
            t = t * (1.0f / (float)NN) + b2[m];
            z[m] = t > 0.f ? t : 0.f;
        }
        for (int j = 0; j < 5; j++) {
            float a = fc1b[j];
            for (int m = 0; m < 5; m++) a += z[m] * fc1W[m * 5 + j];
            z2[j] = a > 0.f ? a : 0.f;
        }
        float y[2];
        for (int t2 = 0; t2 < 2; t2++) {
            float a = fcb[t2];
            for (int j = 0; j < 5; j++) a += z2[j] * fcW[j * 2 + t2];
            y[t2] = 1.0f / (1.0f + expf(-a));
        }
        for (int m = 0; m < 5; m++) if (m < out_size) out[m] = z[m];
        if (out_size > 5) out[5] = y[0];
        if (out_size > 6) out[6] = y[1];
    }
}

// ---------------------------------------------------------------------------
extern "C" void kernel_launch(void* const* d_in, const int* in_sizes, int n_in,
                              void* d_out, int out_size) {
    const float* x    = (const float*)d_in[0];
    const float* adj  = (const float*)d_in[1];
    const float* W1   = (const float*)d_in[2];
    const float* b1   = (const float*)d_in[3];
    const float* W2   = (const float*)d_in[4];
    const float* b2   = (const float*)d_in[5];
    const float* fc1W = (const float*)d_in[6];
    const float* fc1b = (const float*)d_in[7];
    const float* fcW  = (const float*)d_in[8];
    const float* fcb  = (const float*)d_in[9];
    float* out = (float*)d_out;

    // smem: tile 40KB + ring 14*2*512*4=56KB + strips 14*1024*4=56KB = 152KB
    const int smem1 = (KT * JTILE + NW * NSTAGE * 512 + NW * JTILE) * 4;
    cudaFuncSetAttribute(k_pass1, cudaFuncAttributeMaxDynamicSharedMemorySize, smem1);

    k_xw1<<<128, 256>>>(x, W1);                       // also resets g_done
    k_pass1<<<GRIDP, BLKT, smem1>>>(adj);             // ONE adj read: U1+min+colsum+scan
    k_h_s2<<<64, 128>>>(adj, b1, W2);                 // c + s2 + partA/partC
    k_final_b<<<1, 32>>>(b2, fc1W, fc1b, fcW, fcb, out, out_size);
}

// round 17
// speedup vs baseline: 1.3751x; 1.0169x over previous
#include <cuda_runtime.h>
#include <math.h>

#define NN 8192
#define DINV_C 0.011048543456039806f   /* (float)(1/sqrt(8192)) */
#define MAXD 256
#define BLKT 448        /* 14 warps */
#define NW 14
#define RPB 56          /* 14 warps x 4 rows */
#define GRIDP 147       /* ceil(8192/56) <= 148 SMs -> single wave */
#define NSTAGE 2        /* cp.async ring stages per warp */
#define KT 10
#define JTILE 1024
#define IPT (JTILE / 128)
#define NT  (NN / JTILE)
#define GRIDH 64        /* k_h_s2 blocks */

static __device__ float g_s1T[10 * NN];   // XW1 transposed [k][j], UNSCALED
static __device__ float g_U1[NN * 10];    // adj @ XW1
static __device__ float g_minrow[NN];
static __device__ float g_dinv[NN];
static __device__ int   g_defect[MAXD];
static __device__ int   g_ndef;
static __device__ int   g_done;           // pass1 finished-block counter
static __device__ int   g_doneH;          // k_h_s2 finished-block counter
static __device__ float g_colpart[(size_t)GRIDP * NN];  // per-block colsum partials
static __device__ float g_partA[GRIDH * 5];  // sum_i dinv_i * s2[i,m]
static __device__ float g_partC[GRIDH * 5];  // sum_j c_j   * s2[j,m]

// ---------------------------------------------------------------------------
// packed fp32x2 ops — only reachable via PTX on sm_103a
// ---------------------------------------------------------------------------
__device__ __forceinline__ unsigned long long ffma2(unsigned long long a,
                                                    unsigned long long b,
                                                    unsigned long long c) {
    unsigned long long d;
    asm("fma.rn.f32x2 %0, %1, %2, %3;" : "=l"(d) : "l"(a), "l"(b), "l"(c));
    return d;
}
__device__ __forceinline__ unsigned long long fadd2(unsigned long long a,
                                                    unsigned long long b) {
    unsigned long long d;
    asm("add.rn.f32x2 %0, %1, %2;" : "=l"(d) : "l"(a), "l"(b));
    return d;
}
union U64F2 { unsigned long long u; float2 f; };
__device__ __forceinline__ float2 u2f(unsigned long long u) { U64F2 t; t.u = u; return t.f; }

__device__ __forceinline__ void cp_async16(unsigned dst, const float* src) {
    asm volatile("cp.async.cg.shared.global [%0], [%1], 16;" :: "r"(dst), "l"(src));
}

// ---------------------------------------------------------------------------
// K1: s1T[k][i] = (x @ W1)[i][k].  4 lanes per row.  Also resets counters.
// ---------------------------------------------------------------------------
__global__ void __launch_bounds__(256) k_xw1(const float* __restrict__ x,
                                             const float* __restrict__ W1) {
    __shared__ float w[128 * 10];
    int tid = threadIdx.x;
    if (blockIdx.x == 0 && tid == 0) { g_done = 0; g_doneH = 0; }  // replay reset
    for (int t = tid; t < 128 * 10; t += 256) w[t] = W1[t];
    __syncthreads();
    int g = blockIdx.x * 256 + tid;          // 0..32767
    int i = g >> 2, q = g & 3;               // row, quarter
    float acc[10];
#pragma unroll
    for (int k = 0; k < 10; k++) acc[k] = 0.f;
    const float4* xr = (const float4*)(x + (size_t)i * 128 + q * 32);
#pragma unroll
    for (int c4 = 0; c4 < 8; c4++) {
        float4 xv = xr[c4];
        int cb = (q * 32 + c4 * 4) * 10;
#pragma unroll
        for (int k = 0; k < 10; k++) {
            acc[k] += xv.x * w[cb + k];
            acc[k] += xv.y * w[cb + 10 + k];
            acc[k] += xv.z * w[cb + 20 + k];
            acc[k] += xv.w * w[cb + 30 + k];
        }
    }
#pragma unroll
    for (int k = 0; k < 10; k++) {
        acc[k] += __shfl_xor_sync(0xffffffffu, acc[k], 1);
        acc[k] += __shfl_xor_sync(0xffffffffu, acc[k], 2);
    }
    if (q == 0)
#pragma unroll
        for (int k = 0; k < 10; k++) g_s1T[k * NN + i] = acc[k];
}

// ---------------------------------------------------------------------------
// THE single adj pass: U1[i][k] = sum_j adj[i][j]*s1T[k][j], per-row min,
// AND per-block column sums (adj read once: 256MB total DRAM).
// Strips are WRITE-ONCE per tile (each it covers a disjoint 128-float range)
// -> pure STS, no RMW, no zeroing. Invalid warps store zeros.
// LAST finishing block runs dinv scan + defect recount inline.
// ---------------------------------------------------------------------------
__global__ void __launch_bounds__(BLKT, 1) k_pass1(const float* __restrict__ adj) {
    extern __shared__ __align__(16) float smem[];
    float* tile   = smem;                               // KT*JTILE
    float* ring   = smem + KT * JTILE;                  // NW*NSTAGE*512
    float* strips = ring + NW * NSTAGE * 512;           // NW*JTILE
    const int tid  = threadIdx.x;
    const int warp = tid >> 5, lane = tid & 31;
    float* abuf = ring + warp * (NSTAGE * 512);
    float* mystrip = strips + warp * JTILE;
    const unsigned abase = (unsigned)__cvta_generic_to_shared(abuf);

    const int row0 = blockIdx.x * RPB + warp * 4;
    const int row0c = (row0 > NN - 4) ? (NN - 4) : row0;   // clamp: dup reads
    const bool ok = (row0 < NN);
    const float* __restrict__ rp = adj + (size_t)row0c * NN;

    unsigned long long acc[4][KT];
#pragma unroll
    for (int r = 0; r < 4; r++)
#pragma unroll
        for (int k = 0; k < KT; k++) acc[r][k] = 0ull;

    float rmin[4];
#pragma unroll
    for (int r = 0; r < 4; r++) rmin[r] = 3.4e38f;

    const int NSEG = NN / 128;

    // load tile 0 (strips need no init: write-once per tile)
    for (int idx = tid; idx < KT * (JTILE / 4); idx += BLKT) {
        int k = idx / (JTILE / 4), q = idx % (JTILE / 4);
        ((float4*)tile)[idx] = ((const float4*)(g_s1T + (size_t)k * NN))[q];
    }

    // cp.async prologue
#pragma unroll
    for (int s = 0; s < NSTAGE; s++) {
#pragma unroll
        for (int r = 0; r < 4; r++)
            cp_async16(abase + (unsigned)((s * 512 + r * 128 + lane * 4) * 4),
                       rp + (size_t)r * NN + s * 128 + lane * 4);
        asm volatile("cp.async.commit_group;");
    }
    __syncthreads();

    for (int tI = 0; tI < NT; tI++) {
        if (tI > 0) {
            __syncthreads();
            for (int idx = tid; idx < KT * (JTILE / 4); idx += BLKT) {
                int k = idx / (JTILE / 4), q = idx % (JTILE / 4);
                ((float4*)tile)[idx] =
                    ((const float4*)(g_s1T + (size_t)k * NN + (size_t)tI * JTILE))[q];
            }
            __syncthreads();
        }
#pragma unroll 2
        for (int it = 0; it < IPT; it++) {
            const int seg = tI * IPT + it;
            const int js = it * 128 + lane * 4;
            asm volatile("cp.async.wait_group %0;" :: "n"(NSTAGE - 1));
            longlong2 a[4];
#pragma unroll
            for (int r = 0; r < 4; r++)
                a[r] = *(const longlong2*)(abuf + (seg & (NSTAGE - 1)) * 512 + r * 128 + lane * 4);
            {
                const int sn = seg + NSTAGE;
                const int goff = (sn < NSEG) ? sn * 128 : 0;
#pragma unroll
                for (int r = 0; r < 4; r++)
                    cp_async16(abase + (unsigned)(((sn & (NSTAGE - 1)) * 512 + r * 128 + lane * 4) * 4),
                               rp + (size_t)r * NN + goff + lane * 4);
                asm volatile("cp.async.commit_group;");
            }
            // per-row min tracking
#pragma unroll
            for (int r = 0; r < 4; r++) {
                float2 lo = u2f((unsigned long long)a[r].x);
                float2 hi = u2f((unsigned long long)a[r].y);
                rmin[r] = fminf(rmin[r], fminf(fminf(lo.x, lo.y), fminf(hi.x, hi.y)));
            }
            // column-sum strip store (write-once per tile; zeros if clamped dup)
            {
                unsigned long long s0 = 0ull, s1 = 0ull;
                if (ok) {
                    s0 = fadd2(fadd2((unsigned long long)a[0].x, (unsigned long long)a[1].x),
                               fadd2((unsigned long long)a[2].x, (unsigned long long)a[3].x));
                    s1 = fadd2(fadd2((unsigned long long)a[0].y, (unsigned long long)a[1].y),
                               fadd2((unsigned long long)a[2].y, (unsigned long long)a[3].y));
                }
                longlong2 st;
                st.x = (long long)s0; st.y = (long long)s1;
                *(longlong2*)&mystrip[js] = st;
            }
#pragma unroll
            for (int k = 0; k < KT; k++) {
                longlong2 sv = *(const longlong2*)&tile[k * JTILE + js];
#pragma unroll
                for (int r = 0; r < 4; r++) {
                    acc[r][k] = ffma2((unsigned long long)a[r].x, (unsigned long long)sv.x, acc[r][k]);
                    acc[r][k] = ffma2((unsigned long long)a[r].y, (unsigned long long)sv.y, acc[r][k]);
                }
            }
        }
        // tile end: reduce 14 strips -> per-block colsum partial
        __syncthreads();
        {
            const size_t gbase = (size_t)blockIdx.x * NN + (size_t)tI * JTILE;
            for (int idx = tid; idx < JTILE; idx += BLKT) {
                float s = 0.f;
#pragma unroll
                for (int w = 0; w < NW; w++) s += strips[w * JTILE + idx];
                g_colpart[gbase + idx] = s;
            }
        }
    }
    asm volatile("cp.async.wait_group 0;");   // drain dummies

    // epilogue: U1 + minrow
#pragma unroll
    for (int r = 0; r < 4; r++) {
#pragma unroll
        for (int k = 0; k < KT; k++) {
            float2 v = u2f(acc[r][k]);
            float s = v.x + v.y;
#pragma unroll
            for (int o = 16; o > 0; o >>= 1) s += __shfl_xor_sync(0xffffffffu, s, o);
            if (lane == 0 && ok) g_U1[(size_t)(row0c + r) * KT + k] = s;
        }
        float m = rmin[r];
#pragma unroll
        for (int o = 16; o > 0; o >>= 1) m = fminf(m, __shfl_xor_sync(0xffffffffu, m, o));
        if (lane == 0 && ok) g_minrow[row0c + r] = m;
    }

    // fused scan: last finishing block does dinv + defects + recount
    __threadfence();
    __syncthreads();
    __shared__ int s_go;
    if (tid == 0) s_go = (atomicAdd(&g_done, 1) == GRIDP - 1) ? 1 : 0;
    __syncthreads();
    if (s_go) {
        __shared__ int wcnt[NW], woff[NW], sbase;
        if (tid == 0) sbase = 0;
        __syncthreads();
        for (int chunk = 0; chunk < NN; chunk += BLKT) {
            int i = chunk + tid;
            bool valid = (i < NN);
            bool f = valid && (g_minrow[i] <= 0.0f);
            if (valid) g_dinv[i] = DINV_C;
            unsigned m = __ballot_sync(0xffffffffu, f);
            if (lane == 0) wcnt[warp] = __popc(m);
            __syncthreads();
            if (tid == 0) {
                int o = sbase;
                for (int q = 0; q < NW; q++) { woff[q] = o; o += wcnt[q]; }
                sbase = o;
            }
            __syncthreads();
            if (f) {
                int pos = woff[warp] + __popc(m & ((1u << lane) - 1u));
                if (pos < MAXD) g_defect[pos] = i;
            }
            __syncthreads();
        }
        int nd = (sbase > MAXD) ? MAXD : sbase;
        if (tid == 0) g_ndef = nd;
        // exact recount: one warp per defect row (coalesced reads)
        for (int d = warp; d < nd; d += NW) {
            int j = g_defect[d];
            const float4* row = (const float4*)(adj + (size_t)j * NN);
            int cnt = 0;
            for (int t = lane; t < NN / 4; t += 32) {
                float4 v = row[t];
                cnt += (v.x > 0.f) + (v.y > 0.f) + (v.z > 0.f) + (v.w > 0.f);
            }
#pragma unroll
            for (int o = 16; o > 0; o >>= 1) cnt += __shfl_xor_sync(0xffffffffu, cnt, o);
            if (lane == 0)
                g_dinv[j] = (cnt > 0) ? (1.0f / sqrtf((float)cnt))
                                      : __int_as_float(0x7f800000);
        }
    }
}

// ---------------------------------------------------------------------------
// K5: c[j] = DINV_C*colsum[j] + defect correction; h = relu(gcn1);
//     partA[m] = sum_i dinv_i*s2[i,m], partC[m] = sum_j c_j*s2[j,m].
//     LAST finishing block computes the MLP head and writes out (fused).
// ---------------------------------------------------------------------------
__global__ void __launch_bounds__(128) k_h_s2(const float* __restrict__ adj,
                                              const float* __restrict__ b1,
                                              const float* __restrict__ W2,
                                              const float* __restrict__ b2,
                                              const float* __restrict__ fc1W,
                                              const float* __restrict__ fc1b,
                                              const float* __restrict__ fcW,
                                              const float* __restrict__ fcb,
                                              float* __restrict__ out, int out_size) {
    __shared__ float sb1[10], sW2[50];
    __shared__ int   sjd[MAXD];
    __shared__ float sdv[MAXD];
    __shared__ float sxw[MAXD * 10];
    __shared__ int   snd;
    __shared__ float wsA[4][5], wsC[4][5];
    int tid = threadIdx.x, lane = tid & 31, w = tid >> 5;
    if (tid < 10) sb1[tid] = b1[tid];
    if (tid < 50) sW2[tid] = W2[tid];
    if (tid == 0) { int n = g_ndef; snd = (n > MAXD) ? MAXD : n; }
    __syncthreads();
    int nd = snd;
    for (int d = tid; d < nd; d += blockDim.x) {
        int j = g_defect[d];
        sjd[d] = j;
        sdv[d] = g_dinv[j] - DINV_C;
        for (int k = 0; k < 10; k++) sxw[d * 10 + k] = g_s1T[k * NN + j];
    }
    __syncthreads();

    int i = blockIdx.x * blockDim.x + tid;
    float di = g_dinv[i];

    // c[i]: reduce the 147 per-block colsum partials (fixed order) + defect rows
    float cs = 0.f;
#pragma unroll 7
    for (int b = 0; b < GRIDP; b++) cs += g_colpart[(size_t)b * NN + i];
    float ci = DINV_C * cs;
    for (int d = 0; d < nd; d++)
        ci += sdv[d] * adj[(size_t)sjd[d] * NN + i];   // coalesced row reads

    // gcn1 defect correction (column gathers) + h
    float u[10];
#pragma unroll
    for (int k = 0; k < 10; k++) u[k] = DINV_C * g_U1[(size_t)i * 10 + k];
    int d = 0;
    for (; d + 3 < nd; d += 4) {
        float a0 = adj[(size_t)i * NN + sjd[d]]     * sdv[d];
        float a1 = adj[(size_t)i * NN + sjd[d + 1]] * sdv[d + 1];
        float a2 = adj[(size_t)i * NN + sjd[d + 2]] * sdv[d + 2];
        float a3 = adj[(size_t)i * NN + sjd[d + 3]] * sdv[d + 3];
#pragma unroll
        for (int k = 0; k < 10; k++)
            u[k] += a0 * sxw[d * 10 + k] + a1 * sxw[(d + 1) * 10 + k]
                  + a2 * sxw[(d + 2) * 10 + k] + a3 * sxw[(d + 3) * 10 + k];
    }
    for (; d < nd; d++) {
        float a = adj[(size_t)i * NN + sjd[d]] * sdv[d];
#pragma unroll
        for (int k = 0; k < 10; k++) u[k] += a * sxw[d * 10 + k];
    }
    float h[10];
#pragma unroll
    for (int k = 0; k < 10; k++) {
        float self = g_s1T[k * NN + i] * di;
        float v = di * (u[k] + self) + sb1[k];
        h[k] = v > 0.f ? v : 0.f;
    }
    float pa[5], pc[5];
#pragma unroll
    for (int m = 0; m < 5; m++) {
        float s = 0.f;
#pragma unroll
        for (int k = 0; k < 10; k++) s += h[k] * sW2[k * 5 + m];
        float val = s * di;        // s2[i][m]
        pa[m] = di * val;
        pc[m] = ci * val;
    }
#pragma unroll
    for (int m = 0; m < 5; m++) {
        float va = pa[m], vc = pc[m];
#pragma unroll
        for (int o = 16; o > 0; o >>= 1) {
            va += __shfl_xor_sync(0xffffffffu, va, o);
            vc += __shfl_xor_sync(0xffffffffu, vc, o);
        }
        if (lane == 0) { wsA[w][m] = va; wsC[w][m] = vc; }
    }
    __syncthreads();
    if (tid < 5) {
        g_partA[blockIdx.x * 5 + tid] = wsA[0][tid] + wsA[1][tid] + wsA[2][tid] + wsA[3][tid];
        g_partC[blockIdx.x * 5 + tid] = wsC[0][tid] + wsC[1][tid] + wsC[2][tid] + wsC[3][tid];
    }

    // ----- fused head: last finishing block computes z / y and writes out ----
    __threadfence();
    __syncthreads();
    __shared__ int s_go;
    if (tid == 0) s_go = (atomicAdd(&g_doneH, 1) == GRIDH - 1) ? 1 : 0;
    __syncthreads();
    if (s_go && w == 0) {
        float zsh[5];
#pragma unroll
        for (int m = 0; m < 5; m++) {
            float v = 0.f;
            if (lane < 32) {
                v  = g_partA[lane * 5 + m] + g_partA[(lane + 32) * 5 + m];
                v += g_partC[lane * 5 + m] + g_partC[(lane + 32) * 5 + m];
            }
#pragma unroll
            for (int o = 16; o > 0; o >>= 1) v += __shfl_xor_sync(0xffffffffu, v, o);
            zsh[m] = v;
        }
        if (lane == 0) {
            float z[5], z2[5];
            for (int m = 0; m < 5; m++) {
                float t = zsh[m] * (1.0f / (float)NN) + b2[m];
                z[m] = t > 0.f ? t : 0.f;
            }
            for (int j = 0; j < 5; j++) {
                float a = fc1b[j];
                for (int m = 0; m < 5; m++) a += z[m] * fc1W[m * 5 + j];
                z2[j] = a > 0.f ? a : 0.f;
            }
            float y[2];
            for (int t2 = 0; t2 < 2; t2++) {
                float a = fcb[t2];
                for (int j = 0; j < 5; j++) a += z2[j] * fcW[j * 2 + t2];
                y[t2] = 1.0f / (1.0f + expf(-a));
            }
            for (int m = 0; m < 5; m++) if (m < out_size) out[m] = z[m];
            if (out_size > 5) out[5] = y[0];
            if (out_size > 6) out[6] = y[1];
        }
    }
}

// ---------------------------------------------------------------------------
extern "C" void kernel_launch(void* const* d_in, const int* in_sizes, int n_in,
                              void* d_out, int out_size) {
    const float* x    = (const float*)d_in[0];
    const float* adj  = (const float*)d_in[1];
    const float* W1   = (const float*)d_in[2];
    const float* b1   = (const float*)d_in[3];
    const float* W2   = (const float*)d_in[4];
    const float* b2   = (const float*)d_in[5];
    const float* fc1W = (const float*)d_in[6];
    const float* fc1b = (const float*)d_in[7];
    const float* fcW  = (const float*)d_in[8];
    const float* fcb  = (const float*)d_in[9];
    float* out = (float*)d_out;

    // smem: tile 40KB + ring 14*2*512*4=56KB + strips 14*1024*4=56KB = 152KB
    const int smem1 = (KT * JTILE + NW * NSTAGE * 512 + NW * JTILE) * 4;
    cudaFuncSetAttribute(k_pass1, cudaFuncAttributeMaxDynamicSharedMemorySize, smem1);

    k_xw1<<<128, 256>>>(x, W1);                       // also resets door counters
    k_pass1<<<GRIDP, BLKT, smem1>>>(adj);             // ONE adj read: U1+min+colsum+scan
    k_h_s2<<<GRIDH, 128>>>(adj, b1, W2, b2, fc1W, fc1b, fcW, fcb, out, out_size);
}